// round 6
// baseline (speedup 1.0000x reference)
#include <cuda_runtime.h>
#include <cuda_fp16.h>
#include <mma.h>
#include <cstdint>

using namespace nvcuda;

// Arch-specific (sm_10xa) feature gate: tcgen05/TMEM only exist on 'a' targets.
#if defined(__CUDA_ARCH_FEAT_SM103_ALL) || defined(__CUDA_ARCH_FEAT_SM100_ALL) || defined(__CUDA_ARCH_SPECIFIC__)
#define HAS_TC 1
#else
#define HAS_TC 0
#endif

// Problem constants
constexpr int Bn = 4096;
constexpr int Nn = 8192;
constexpr int Dn = 1024;
constexpr float DROP_SCALE = 1.0f / 0.75f;
constexpr float EPS = 1e-5f;

// tcgen05 tiling: CTA computes 128 (M) x 256 (N), K-tile = 64 fp16, 4 stages
constexpr int TM = 128;
constexpr int TN = 256;
constexpr int TK = 64;
constexpr int STAGES = 4;
constexpr uint32_t IDESC = (1u << 4) | ((TN / 8) << 17) | ((TM / 16) << 24);

// smem: header 1KB (tmem ptr @0, load_full mbars @64+8s, mma_done @128+8s),
// then 4 stages of (A 16KB + B 32KB)
constexpr uint32_t STAGE_BYTES = 49152;
constexpr uint32_t SM_TILES = 1024;
constexpr uint32_t SMEM_BYTES = SM_TILES + STAGES * STAGE_BYTES;   // 197632

// Device-global scratch (no cudaMalloc allowed)
__device__ __half g_h[(size_t)Bn * Nn];       // 64MB: dropout-scaled x, fp16
__device__ __half g_Wh[(size_t)Dn * Nn];      // 16MB: W fp16 (k-major rows d)
__device__ __half g_Wt[(size_t)Nn * Dn];      // 16MB: W^T fp16 (k-major rows n)
__device__ float  g_enc[(size_t)Bn * Dn];     // 16MB: enc (post-tanh) fp32
__device__ __half g_ench[(size_t)Bn * Dn];    // 8MB: enc fp16
__device__ float  g_errp[(size_t)Bn * 64];
__device__ float  g_cntp[(size_t)Bn * 64];
__device__ float  g_lossp[32];

__device__ __forceinline__ uint32_t smem_u32(const void* p) {
    uint32_t a;
    asm("{ .reg .u64 t; cvta.to.shared.u64 t, %1; cvt.u32.u64 %0, t; }" : "=r"(a) : "l"(p));
    return a;
}

#if HAS_TC
// ---------------------------------------------------------------------------
// tcgen05 helpers (sm_103a only)
// ---------------------------------------------------------------------------
__device__ __forceinline__ bool elect_one() {
    uint32_t pred;
    asm volatile("{\n\t.reg .pred p;\n\telect.sync _|p, 0xFFFFFFFF;\n\tselp.b32 %0, 1, 0, p;\n\t}"
                 : "=r"(pred));
    return pred != 0;
}
__device__ __forceinline__ void mbar_init(uint32_t a, uint32_t cnt) {
    asm volatile("mbarrier.init.shared.b64 [%0], %1;" :: "r"(a), "r"(cnt) : "memory");
}
__device__ __forceinline__ void mbar_wait(uint32_t a, uint32_t parity) {
    asm volatile(
        "{\n\t.reg .pred P;\n\t"
        "WL_%=:\n\t"
        "mbarrier.try_wait.parity.acquire.cta.shared::cta.b64 P, [%0], %1, 0x989680;\n\t"
        "@P bra WD_%=;\n\t"
        "bra WL_%=;\n\t"
        "WD_%=:\n\t}"
        :: "r"(a), "r"(parity) : "memory");
}
__device__ __forceinline__ void cp16(uint32_t s, const void* g) {
    asm volatile("cp.async.cg.shared.global [%0], [%1], 16;" :: "r"(s), "l"(g));
}
__device__ __forceinline__ void cpasync_arrive(uint32_t mbar) {
    asm volatile("cp.async.mbarrier.arrive.noinc.shared.b64 [%0];" :: "r"(mbar) : "memory");
}
__device__ __forceinline__ void mma_f16_ss(uint32_t d, uint64_t ad, uint64_t bd,
                                           uint32_t idesc, bool acc) {
    uint32_t en = acc ? 1u : 0u;
    asm volatile(
        "{\n\t.reg .pred p;\n\tsetp.ne.u32 p, %5, 0;\n\t"
        "tcgen05.mma.cta_group::1.kind::f16 [%0], %1, %2, %3, {%4, %4, %4, %4}, p;\n\t}"
        :: "r"(d), "l"(ad), "l"(bd), "r"(idesc), "r"(0u), "r"(en) : "memory");
}
__device__ __forceinline__ void tc_commit(uint32_t mbar) {
    asm volatile(
        "tcgen05.commit.cta_group::1.mbarrier::arrive::one.shared::cluster.b64 [%0];"
        :: "r"(mbar) : "memory");
}
__device__ __forceinline__ uint64_t mk_desc(uint32_t addr) {
    constexpr uint64_t BASE = (uint64_t(2) << 61) | (uint64_t(1) << 46) |
                              (uint64_t(64) << 32) | (uint64_t(1) << 16);
    return BASE | ((uint64_t)(addr >> 4) & 0x3FFF);
}
#define TC_ALLOC(sm, n)   asm volatile("tcgen05.alloc.cta_group::1.sync.aligned.shared::cta.b32 [%0], %1;" :: "r"(sm), "r"(n) : "memory")
#define TC_DEALLOC(t, n)  asm volatile("tcgen05.dealloc.cta_group::1.sync.aligned.b32 %0, %1;" :: "r"(t), "r"(n))
#define TC_RELINQ()       asm volatile("tcgen05.relinquish_alloc_permit.cta_group::1.sync.aligned;")
#define TC_FENCE_AFTER()  asm volatile("tcgen05.fence::after_thread_sync;" ::: "memory")
#define TC_FENCE_BEFORE() asm volatile("tcgen05.fence::before_thread_sync;" ::: "memory")
#define TC_WAIT_LD()      asm volatile("tcgen05.wait::ld.sync.aligned;" ::: "memory")

#define LDTM_X32(r, a) \
    asm volatile("tcgen05.ld.sync.aligned.32x32b.x32.b32 " \
        "{%0,%1,%2,%3,%4,%5,%6,%7,%8,%9,%10,%11,%12,%13,%14,%15," \
        "%16,%17,%18,%19,%20,%21,%22,%23,%24,%25,%26,%27,%28,%29,%30,%31}, [%32];" \
        : "=r"((r)[0]),"=r"((r)[1]),"=r"((r)[2]),"=r"((r)[3]),"=r"((r)[4]),"=r"((r)[5]), \
          "=r"((r)[6]),"=r"((r)[7]),"=r"((r)[8]),"=r"((r)[9]),"=r"((r)[10]),"=r"((r)[11]), \
          "=r"((r)[12]),"=r"((r)[13]),"=r"((r)[14]),"=r"((r)[15]),"=r"((r)[16]),"=r"((r)[17]), \
          "=r"((r)[18]),"=r"((r)[19]),"=r"((r)[20]),"=r"((r)[21]),"=r"((r)[22]),"=r"((r)[23]), \
          "=r"((r)[24]),"=r"((r)[25]),"=r"((r)[26]),"=r"((r)[27]),"=r"((r)[28]),"=r"((r)[29]), \
          "=r"((r)[30]),"=r"((r)[31]) : "r"(a))

// ---------------------------------------------------------------------------
// 4-stage pipelined mainloop: C[128x256] = A[128xK] * B[256xK]^T, fp16 SS.
// load_full[s]: count=256, cp.async.mbarrier.arrive.noinc from every thread.
// mma_done[s]:  count=1, tcgen05.commit target (WAR guard for refills).
// No per-iteration __syncthreads.
// ---------------------------------------------------------------------------
__device__ __forceinline__ uint32_t gemm_mainloop(
    const __half* __restrict__ Ag, const __half* __restrict__ Bg,
    int lda, int ldb, int row0, int nrow0, int tiles, uint32_t sb)
{
    const int tid = threadIdx.x;
    const int wid = tid >> 5;

    if (wid == 0) TC_ALLOC(sb, 256);
    if (tid == 0) {
        #pragma unroll
        for (int s = 0; s < STAGES; ++s) {
            mbar_init(sb + 64 + 8 * s, 256);    // load_full
            mbar_init(sb + 128 + 8 * s, 1);     // mma_done
        }
    }
    __syncthreads();
    if (wid == 0) TC_RELINQ();
    uint32_t tmem;
    asm volatile("ld.shared.b32 %0, [%1];" : "=r"(tmem) : "r"(sb));

    uint32_t lf_ph = 0, md_ph = 0;   // per-stage parity bitmasks
    for (int kt = 0; kt < tiles; ++kt) {
        const int s = kt & (STAGES - 1);
        const uint32_t stage = sb + SM_TILES + s * STAGE_BYTES;
        if (kt >= STAGES) {
            mbar_wait(sb + 128 + 8 * s, (md_ph >> s) & 1u);
            md_ph ^= 1u << s;
        }
        const int kbase = kt * TK;
        // A: 128 rows x 8 x 16B-chunks (SW128 swizzle)
        #pragma unroll
        for (int i = 0; i < 4; ++i) {
            const int ch = tid + i * 256;
            const int r = ch >> 3, c = ch & 7;
            const uint32_t bo = (r << 7) | (c << 4);
            cp16(stage + (bo ^ ((bo >> 3) & 0x70)),
                 Ag + (size_t)(row0 + r) * lda + kbase + (c << 3));
        }
        // B: 256 rows x 8 x 16B-chunks
        #pragma unroll
        for (int i = 0; i < 8; ++i) {
            const int ch = tid + i * 256;
            const int r = ch >> 3, c = ch & 7;
            const uint32_t bo = (r << 7) | (c << 4);
            cp16(stage + 16384 + (bo ^ ((bo >> 3) & 0x70)),
                 Bg + (size_t)(nrow0 + r) * ldb + kbase + (c << 3));
        }
        cpasync_arrive(sb + 64 + 8 * s);

        if (wid == 0) {   // consumer: whole warp stays converged
            mbar_wait(sb + 64 + 8 * s, (lf_ph >> s) & 1u);
            lf_ph ^= 1u << s;
            asm volatile("fence.proxy.async.shared::cta;" ::: "memory");
            if (elect_one()) {
                const uint64_t ad = mk_desc(stage);
                const uint64_t bd = mk_desc(stage + 16384);
                #pragma unroll
                for (int ks = 0; ks < 4; ++ks)
                    mma_f16_ss(tmem, ad + 2 * ks, bd + 2 * ks, IDESC, (kt > 0) || ks > 0);
                tc_commit(sb + 128 + 8 * s);
            }
        }
    }
    // Final commit tracks ALL prior MMAs: one wait suffices.
    const int sl = (tiles - 1) & (STAGES - 1);
    mbar_wait(sb + 128 + 8 * sl, (md_ph >> sl) & 1u);
    TC_FENCE_AFTER();
    return tmem;
}
#endif  // HAS_TC

// ---------------------------------------------------------------------------
// Fallback (non-'a' PTX pass): wmma fp16 m16n16k16, 128x128 half-tile helper.
// ---------------------------------------------------------------------------
__device__ __forceinline__ void fb_gemm128(
    const __half* __restrict__ Ag, int lda, const __half* __restrict__ Bg, int ldb,
    int row0, int nrow0, int K, char* smem, float* Cs)
{
    __half* As = reinterpret_cast<__half*>(smem);
    __half* Bs = reinterpret_cast<__half*>(smem + 128 * 40 * 2);
    const int tid = threadIdx.x;
    const int wid = tid >> 5;
    const int wm = wid & 1, wn = wid >> 1;

    wmma::fragment<wmma::accumulator, 16, 16, 16, float> acc[4][2];
    #pragma unroll
    for (int i = 0; i < 4; i++)
        #pragma unroll
        for (int j = 0; j < 2; j++)
            wmma::fill_fragment(acc[i][j], 0.0f);

    for (int kt = 0; kt < K / 32; ++kt) {
        const int kb = kt * 32;
        #pragma unroll
        for (int i = 0; i < 2; ++i) {
            const int v = tid + i * 256;
            const int r = v >> 2, c = (v & 3) * 8;
            *reinterpret_cast<uint4*>(&As[r * 40 + c]) =
                *reinterpret_cast<const uint4*>(&Ag[(size_t)(row0 + r) * lda + kb + c]);
            *reinterpret_cast<uint4*>(&Bs[r * 40 + c]) =
                *reinterpret_cast<const uint4*>(&Bg[(size_t)(nrow0 + r) * ldb + kb + c]);
        }
        __syncthreads();
        #pragma unroll
        for (int kk = 0; kk < 32; kk += 16) {
            wmma::fragment<wmma::matrix_a, 16, 16, 16, __half, wmma::row_major> af[4];
            wmma::fragment<wmma::matrix_b, 16, 16, 16, __half, wmma::col_major> bf[2];
            #pragma unroll
            for (int fm = 0; fm < 4; fm++)
                wmma::load_matrix_sync(af[fm], &As[(wm * 64 + fm * 16) * 40 + kk], 40);
            #pragma unroll
            for (int fn = 0; fn < 2; fn++)
                wmma::load_matrix_sync(bf[fn], &Bs[(wn * 32 + fn * 16) * 40 + kk], 40);
            #pragma unroll
            for (int fm = 0; fm < 4; fm++)
                #pragma unroll
                for (int fn = 0; fn < 2; fn++)
                    wmma::mma_sync(acc[fm][fn], af[fm], bf[fn], acc[fm][fn]);
        }
        __syncthreads();
    }
    #pragma unroll
    for (int fm = 0; fm < 4; fm++)
        #pragma unroll
        for (int fn = 0; fn < 2; fn++)
            wmma::store_matrix_sync(&Cs[(wm * 64 + fm * 16) * 132 + wn * 32 + fn * 16],
                                    acc[fm][fn], 132, wmma::mem_row_major);
    __syncthreads();
}

// ---------------------------------------------------------------------------
// GEMM1: enc = tanh(h @ Wh^T + b1) -> g_enc (fp32) + g_ench (fp16)
// grid: (Dn/TN=4, Bn/TM=32), 256 threads
// ---------------------------------------------------------------------------
__global__ __launch_bounds__(256) void gemm1_kernel(const float* __restrict__ b1)
{
    extern __shared__ __align__(1024) char smem[];
    const int row0 = blockIdx.y * TM;
    const int col0 = blockIdx.x * TN;
    const int tid = threadIdx.x;
    const int wid = tid >> 5;

#if HAS_TC
    const uint32_t sb = smem_u32(smem);
    const uint32_t tmem = gemm_mainloop(g_h, g_Wh, Nn, Nn, row0, col0, Nn / TK, sb);

    const int lane = tid & 31;
    const int team = wid >> 2;
    const int r = ((wid & 3) << 5) + lane;
    const size_t grow = row0 + r;
    #pragma unroll
    for (int chunk = 0; chunk < 4; ++chunk) {
        const int c0 = team * 128 + chunk * 32;
        uint32_t regs[32];
        LDTM_X32(regs, tmem + c0);
        TC_WAIT_LD();
        #pragma unroll
        for (int j = 0; j < 32; j += 2) {
            const int d = col0 + c0 + j;
            const float e0 = tanhf(__uint_as_float(regs[j])     + b1[d]);
            const float e1 = tanhf(__uint_as_float(regs[j + 1]) + b1[d + 1]);
            g_enc[grow * Dn + d]     = e0;
            g_enc[grow * Dn + d + 1] = e1;
            *reinterpret_cast<__half2*>(&g_ench[grow * Dn + d]) = __floats2half2_rn(e0, e1);
        }
    }
    TC_FENCE_BEFORE();
    __syncthreads();
    if (wid == 0) TC_DEALLOC(tmem, 256);
#else
    float* Cs = reinterpret_cast<float*>(smem);
    for (int hf = 0; hf < 2; ++hf) {
        fb_gemm128(g_h, Nn, g_Wh, Nn, row0, col0 + hf * 128, Nn, smem, Cs);
        #pragma unroll 4
        for (int t = 0; t < 32; ++t) {
            const int p = tid + t * 256;
            const int r = p >> 6, c2 = (p & 63) * 2;
            const int d = col0 + hf * 128 + c2;
            const size_t grow = row0 + r;
            const float e0 = tanhf(Cs[r * 132 + c2]     + b1[d]);
            const float e1 = tanhf(Cs[r * 132 + c2 + 1] + b1[d + 1]);
            g_enc[grow * Dn + d]     = e0;
            g_enc[grow * Dn + d + 1] = e1;
            *reinterpret_cast<__half2*>(&g_ench[grow * Dn + d]) = __floats2half2_rn(e0, e1);
        }
        __syncthreads();
    }
#endif
}

// ---------------------------------------------------------------------------
// GEMM2: recon = ench @ Wt^T + b2 (never stored); fused masked-MSE partials
// grid: (Nn/TN=32, Bn/TM=32)
// ---------------------------------------------------------------------------
__global__ __launch_bounds__(256) void gemm2_kernel(
    const float* __restrict__ x, const float* __restrict__ b2)
{
    extern __shared__ __align__(1024) char smem[];
    const int row0 = blockIdx.y * TM;
    const int nb = blockIdx.x;
    const int n0 = nb * TN;
    const int tid = threadIdx.x;
    const int wid = tid >> 5;
    const int lane = tid & 31;

#if HAS_TC
    const uint32_t sb = smem_u32(smem);
    const uint32_t tmem = gemm_mainloop(g_ench, g_Wt, Dn, Dn, row0, n0, Dn / TK, sb);

    const int team = wid >> 2;
    const int r = ((wid & 3) << 5) + lane;
    const size_t grow = row0 + r;
    float err = 0.f, cnt = 0.f;
    #pragma unroll
    for (int chunk = 0; chunk < 4; ++chunk) {
        const int c0 = team * 128 + chunk * 32;
        uint32_t regs[32];
        LDTM_X32(regs, tmem + c0);
        TC_WAIT_LD();
        const float* xr = x + grow * Nn + n0 + c0;
        const float* b2r = b2 + n0 + c0;
        #pragma unroll
        for (int j = 0; j < 32; ++j) {
            const float recon = __uint_as_float(regs[j]) + b2r[j];
            const float xv = xr[j];
            if (xv != 0.0f) {
                const float d = xv - recon;
                err += d * d;
                cnt += 1.0f;
            }
        }
    }
    g_errp[grow * 64 + nb * 2 + team] = err;
    g_cntp[grow * 64 + nb * 2 + team] = cnt;

    TC_FENCE_BEFORE();
    __syncthreads();
    if (wid == 0) TC_DEALLOC(tmem, 256);
#else
    float* Cs = reinterpret_cast<float*>(smem);
    for (int hf = 0; hf < 2; ++hf) {
        fb_gemm128(g_ench, Dn, g_Wt, Dn, row0, n0 + hf * 128, Dn, smem, Cs);
        for (int rr = 0; rr < 16; ++rr) {
            const int r = wid * 16 + rr;
            const size_t brow = row0 + r;
            float err = 0.f, cnt = 0.f;
            #pragma unroll
            for (int s4 = 0; s4 < 4; ++s4) {
                const int c = s4 * 32 + lane;
                const float recon = Cs[r * 132 + c] + b2[n0 + hf * 128 + c];
                const float xv = x[brow * Nn + n0 + hf * 128 + c];
                if (xv != 0.0f) {
                    const float d = xv - recon;
                    err += d * d;
                    cnt += 1.0f;
                }
            }
            #pragma unroll
            for (int o = 16; o; o >>= 1) {
                err += __shfl_xor_sync(0xffffffffu, err, o);
                cnt += __shfl_xor_sync(0xffffffffu, cnt, o);
            }
            if (lane == 0) {
                g_errp[brow * 64 + nb * 2 + hf] = err;
                g_cntp[brow * 64 + nb * 2 + hf] = cnt;
            }
        }
        __syncthreads();
    }
#endif
}

// ---------------------------------------------------------------------------
// Pre-pass conversions
// ---------------------------------------------------------------------------
__global__ void conv_h_kernel(const float4* __restrict__ x, const float4* __restrict__ m)
{
    const size_t i = (size_t)blockIdx.x * blockDim.x + threadIdx.x;
    const float4 xv = x[i], mv = m[i];
    __half2* o = reinterpret_cast<__half2*>(g_h) + 2 * i;
    o[0] = __floats2half2_rn(xv.x * mv.x * DROP_SCALE, xv.y * mv.y * DROP_SCALE);
    o[1] = __floats2half2_rn(xv.z * mv.z * DROP_SCALE, xv.w * mv.w * DROP_SCALE);
}

// Merged W prep: read W once; emit g_Wh (same layout) and g_Wt (transposed)
__global__ void wprep_kernel(const float* __restrict__ W)
{
    __shared__ __half t[32][33];
    const int n0 = blockIdx.x * 32, d0 = blockIdx.y * 32;
    const int tx = threadIdx.x, ty = threadIdx.y;
    #pragma unroll
    for (int i = ty; i < 32; i += 8) {
        const __half v = __float2half_rn(W[(size_t)(d0 + i) * Nn + n0 + tx]);
        g_Wh[(size_t)(d0 + i) * Nn + n0 + tx] = v;
        t[i][tx] = v;
    }
    __syncthreads();
    #pragma unroll
    for (int i = ty; i < 32; i += 8)
        g_Wt[(size_t)(n0 + i) * Dn + d0 + tx] = t[tx][i];
}

// ---------------------------------------------------------------------------
// LayerNorm over D per row -> out[0 : B*D)
// ---------------------------------------------------------------------------
__global__ __launch_bounds__(256) void ln_kernel(
    const float* __restrict__ gamma, const float* __restrict__ beta,
    float* __restrict__ out)
{
    const int row = blockIdx.x;
    const int tid = threadIdx.x;
    const float* rp = g_enc + (size_t)row * Dn;
    float e[4], s = 0.f, ss = 0.f;
    #pragma unroll
    for (int j = 0; j < 4; j++) {
        e[j] = rp[tid + j * 256];
        s += e[j];
        ss += e[j] * e[j];
    }
    #pragma unroll
    for (int o = 16; o; o >>= 1) {
        s  += __shfl_xor_sync(0xffffffffu, s, o);
        ss += __shfl_xor_sync(0xffffffffu, ss, o);
    }
    __shared__ float r1[8], r2[8];
    __shared__ float sh_mu, sh_rstd;
    if ((tid & 31) == 0) { r1[tid >> 5] = s; r2[tid >> 5] = ss; }
    __syncthreads();
    if (tid == 0) {
        float ts = 0.f, tss = 0.f;
        #pragma unroll
        for (int k = 0; k < 8; k++) { ts += r1[k]; tss += r2[k]; }
        const float mu = ts * (1.0f / Dn);
        const float var = tss * (1.0f / Dn) - mu * mu;
        sh_mu = mu;
        sh_rstd = rsqrtf(var + EPS);
    }
    __syncthreads();
    const float mu = sh_mu, rstd = sh_rstd;
    #pragma unroll
    for (int j = 0; j < 4; j++) {
        const int d = tid + j * 256;
        out[(size_t)row * Dn + d] = (e[j] - mu) * rstd * gamma[d] + beta[d];
    }
}

// ---------------------------------------------------------------------------
// Loss reduction (fixed order, no atomics)
// ---------------------------------------------------------------------------
__global__ void reduce1_kernel()
{
    const int row = blockIdx.x * 128 + threadIdx.x;
    float err = 0.f, cnt = 0.f;
    #pragma unroll 8
    for (int j = 0; j < 64; ++j) {
        err += g_errp[(size_t)row * 64 + j];
        cnt += g_cntp[(size_t)row * 64 + j];
    }
    __shared__ float sh[128];
    sh[threadIdx.x] = err / cnt;
    __syncthreads();
    for (int s = 64; s > 0; s >>= 1) {
        if (threadIdx.x < s) sh[threadIdx.x] += sh[threadIdx.x + s];
        __syncthreads();
    }
    if (threadIdx.x == 0) g_lossp[blockIdx.x] = sh[0];
}

__global__ void reduce2_kernel(float* __restrict__ out)
{
    float v = g_lossp[threadIdx.x];
    #pragma unroll
    for (int o = 16; o; o >>= 1) v += __shfl_xor_sync(0xffffffffu, v, o);
    if (threadIdx.x == 0) out[(size_t)Bn * Dn] = v;
}

// ---------------------------------------------------------------------------
// Entry. Inputs: x, drop_mask, W, b1, b2, gamma, beta.
// Output: final [B, D] then recon_loss scalar at out[B*D].
// ---------------------------------------------------------------------------
extern "C" void kernel_launch(void* const* d_in, const int* in_sizes, int n_in,
                              void* d_out, int out_size)
{
    const float* x     = (const float*)d_in[0];
    const float* mask  = (const float*)d_in[1];
    const float* W     = (const float*)d_in[2];
    const float* b1    = (const float*)d_in[3];
    const float* b2    = (const float*)d_in[4];
    const float* gamma = (const float*)d_in[5];
    const float* beta  = (const float*)d_in[6];
    float* out = (float*)d_out;

    cudaFuncSetAttribute(gemm1_kernel, cudaFuncAttributeMaxDynamicSharedMemorySize, SMEM_BYTES);
    cudaFuncSetAttribute(gemm2_kernel, cudaFuncAttributeMaxDynamicSharedMemorySize, SMEM_BYTES);

    conv_h_kernel<<<(Bn * (Nn / 4)) / 256, 256>>>((const float4*)x, (const float4*)mask);
    wprep_kernel<<<dim3(Nn / 32, Dn / 32), dim3(32, 8)>>>(W);
    gemm1_kernel<<<dim3(Dn / TN, Bn / TM), 256, SMEM_BYTES>>>(b1);
    ln_kernel<<<Bn, 256>>>(gamma, beta, out);
    gemm2_kernel<<<dim3(Nn / TN, Bn / TM), 256, SMEM_BYTES>>>(x, b2);
    reduce1_kernel<<<32, 128>>>();
    reduce2_kernel<<<1, 32>>>(out);
}

// round 7
// speedup vs baseline: 1.3557x; 1.3557x over previous
#include <cuda_runtime.h>
#include <cuda_fp16.h>
#include <mma.h>
#include <cstdint>

using namespace nvcuda;

// Arch-specific (sm_10xa) feature gate: tcgen05/TMEM only exist on 'a' targets.
#if defined(__CUDA_ARCH_FEAT_SM103_ALL) || defined(__CUDA_ARCH_FEAT_SM100_ALL) || defined(__CUDA_ARCH_SPECIFIC__)
#define HAS_TC 1
#else
#define HAS_TC 0
#endif

// Problem constants
constexpr int Bn = 4096;
constexpr int Nn = 8192;
constexpr int Dn = 1024;
constexpr float DROP_SCALE = 1.0f / 0.75f;
constexpr float EPS = 1e-5f;

// tcgen05 tiling: CTA computes 128 (M) x 256 (N), K-tile = 64 fp16, 4 stages
constexpr int TM = 128;
constexpr int TN = 256;
constexpr int TK = 64;
constexpr int STAGES = 4;
constexpr uint32_t IDESC = (1u << 4) | ((TN / 8) << 17) | ((TM / 16) << 24);

// smem: header 1KB (tmem ptr @0, mma_done mbars @128+8s), then 4 stages
constexpr uint32_t STAGE_BYTES = 49152;     // A 16KB + B 32KB
constexpr uint32_t SM_TILES = 1024;
constexpr uint32_t SMEM_BYTES = SM_TILES + STAGES * STAGE_BYTES;   // 197632

// Device-global scratch (no cudaMalloc allowed)
__device__ __half g_h[(size_t)Bn * Nn];       // 64MB: dropout-scaled x, fp16
__device__ __half g_Wh[(size_t)Dn * Nn];      // 16MB: W fp16 (k-major rows d)
__device__ __half g_Wt[(size_t)Nn * Dn];      // 16MB: W^T fp16 (k-major rows n)
__device__ float  g_enc[(size_t)Bn * Dn];     // 16MB: enc (post-tanh) fp32
__device__ __half g_ench[(size_t)Bn * Dn];    // 8MB: enc fp16
__device__ float  g_errp[(size_t)Bn * 64];
__device__ float  g_cntp[(size_t)Bn * 64];
__device__ float  g_lossp[32];

__device__ __forceinline__ uint32_t smem_u32(const void* p) {
    uint32_t a;
    asm("{ .reg .u64 t; cvta.to.shared.u64 t, %1; cvt.u32.u64 %0, t; }" : "=r"(a) : "l"(p));
    return a;
}

#if HAS_TC
// ---------------------------------------------------------------------------
// tcgen05 helpers (sm_103a only)
// ---------------------------------------------------------------------------
__device__ __forceinline__ bool elect_one() {
    uint32_t pred;
    asm volatile("{\n\t.reg .pred p;\n\telect.sync _|p, 0xFFFFFFFF;\n\tselp.b32 %0, 1, 0, p;\n\t}"
                 : "=r"(pred));
    return pred != 0;
}
__device__ __forceinline__ void mbar_init(uint32_t a, uint32_t cnt) {
    asm volatile("mbarrier.init.shared.b64 [%0], %1;" :: "r"(a), "r"(cnt) : "memory");
}
__device__ __forceinline__ void mbar_wait(uint32_t a, uint32_t parity) {
    asm volatile(
        "{\n\t.reg .pred P;\n\t"
        "WL_%=:\n\t"
        "mbarrier.try_wait.parity.acquire.cta.shared::cta.b64 P, [%0], %1, 0x989680;\n\t"
        "@P bra WD_%=;\n\t"
        "bra WL_%=;\n\t"
        "WD_%=:\n\t}"
        :: "r"(a), "r"(parity) : "memory");
}
__device__ __forceinline__ void cp16(uint32_t s, const void* g) {
    asm volatile("cp.async.cg.shared.global [%0], [%1], 16;" :: "r"(s), "l"(g));
}
__device__ __forceinline__ void mma_f16_ss(uint32_t d, uint64_t ad, uint64_t bd,
                                           uint32_t idesc, bool acc) {
    uint32_t en = acc ? 1u : 0u;
    asm volatile(
        "{\n\t.reg .pred p;\n\tsetp.ne.u32 p, %5, 0;\n\t"
        "tcgen05.mma.cta_group::1.kind::f16 [%0], %1, %2, %3, {%4, %4, %4, %4}, p;\n\t}"
        :: "r"(d), "l"(ad), "l"(bd), "r"(idesc), "r"(0u), "r"(en) : "memory");
}
__device__ __forceinline__ void tc_commit(uint32_t mbar) {
    asm volatile(
        "tcgen05.commit.cta_group::1.mbarrier::arrive::one.shared::cluster.b64 [%0];"
        :: "r"(mbar) : "memory");
}
__device__ __forceinline__ uint64_t mk_desc(uint32_t addr) {
    constexpr uint64_t BASE = (uint64_t(2) << 61) | (uint64_t(1) << 46) |
                              (uint64_t(64) << 32) | (uint64_t(1) << 16);
    return BASE | ((uint64_t)(addr >> 4) & 0x3FFF);
}
#define TC_ALLOC(sm, n)   asm volatile("tcgen05.alloc.cta_group::1.sync.aligned.shared::cta.b32 [%0], %1;" :: "r"(sm), "r"(n) : "memory")
#define TC_DEALLOC(t, n)  asm volatile("tcgen05.dealloc.cta_group::1.sync.aligned.b32 %0, %1;" :: "r"(t), "r"(n))
#define TC_RELINQ()       asm volatile("tcgen05.relinquish_alloc_permit.cta_group::1.sync.aligned;")
#define TC_FENCE_AFTER()  asm volatile("tcgen05.fence::after_thread_sync;" ::: "memory")
#define TC_FENCE_BEFORE() asm volatile("tcgen05.fence::before_thread_sync;" ::: "memory")
#define TC_WAIT_LD()      asm volatile("tcgen05.wait::ld.sync.aligned;" ::: "memory")

#define LDTM_X32(r, a) \
    asm volatile("tcgen05.ld.sync.aligned.32x32b.x32.b32 " \
        "{%0,%1,%2,%3,%4,%5,%6,%7,%8,%9,%10,%11,%12,%13,%14,%15," \
        "%16,%17,%18,%19,%20,%21,%22,%23,%24,%25,%26,%27,%28,%29,%30,%31}, [%32];" \
        : "=r"((r)[0]),"=r"((r)[1]),"=r"((r)[2]),"=r"((r)[3]),"=r"((r)[4]),"=r"((r)[5]), \
          "=r"((r)[6]),"=r"((r)[7]),"=r"((r)[8]),"=r"((r)[9]),"=r"((r)[10]),"=r"((r)[11]), \
          "=r"((r)[12]),"=r"((r)[13]),"=r"((r)[14]),"=r"((r)[15]),"=r"((r)[16]),"=r"((r)[17]), \
          "=r"((r)[18]),"=r"((r)[19]),"=r"((r)[20]),"=r"((r)[21]),"=r"((r)[22]),"=r"((r)[23]), \
          "=r"((r)[24]),"=r"((r)[25]),"=r"((r)[26]),"=r"((r)[27]),"=r"((r)[28]),"=r"((r)[29]), \
          "=r"((r)[30]),"=r"((r)[31]) : "r"(a))

// ---------------------------------------------------------------------------
// 4-stage, lag-2 mainloop: C[128x256] = A[128xK] * B[256xK]^T, fp16 SS.
// Pacing: per-thread cp.async.wait_group + one __syncthreads per iter
// (cheap, proven in round 4). mma_done[s] (count=1) guards stage refills;
// with 4 stages the guarded MMA was issued 2 iterations earlier => ~0 wait.
// ---------------------------------------------------------------------------
__device__ __forceinline__ void issue_tile_loads(
    const __half* __restrict__ Ag, const __half* __restrict__ Bg,
    int lda, int ldb, int row0, int nrow0, int kbase, uint32_t stage, int tid)
{
    #pragma unroll
    for (int i = 0; i < 4; ++i) {            // A: 128 rows x 8 x 16B
        const int ch = tid + i * 256;
        const int r = ch >> 3, c = ch & 7;
        const uint32_t bo = (r << 7) | (c << 4);
        cp16(stage + (bo ^ ((bo >> 3) & 0x70)),
             Ag + (size_t)(row0 + r) * lda + kbase + (c << 3));
    }
    #pragma unroll
    for (int i = 0; i < 8; ++i) {            // B: 256 rows x 8 x 16B
        const int ch = tid + i * 256;
        const int r = ch >> 3, c = ch & 7;
        const uint32_t bo = (r << 7) | (c << 4);
        cp16(stage + 16384 + (bo ^ ((bo >> 3) & 0x70)),
             Bg + (size_t)(nrow0 + r) * ldb + kbase + (c << 3));
    }
    asm volatile("cp.async.commit_group;");
}

__device__ __forceinline__ void issue_tile_mma(
    uint32_t sb, uint32_t tmem, int t)    // MMA for tile t (warp0, converged)
{
    asm volatile("fence.proxy.async.shared::cta;" ::: "memory");
    if (elect_one()) {
        const uint32_t stage = sb + SM_TILES + (t & (STAGES - 1)) * STAGE_BYTES;
        const uint64_t ad = mk_desc(stage);
        const uint64_t bd = mk_desc(stage + 16384);
        #pragma unroll
        for (int ks = 0; ks < 4; ++ks)
            mma_f16_ss(tmem, ad + 2 * ks, bd + 2 * ks, IDESC, (t > 0) || ks > 0);
        tc_commit(sb + 128 + 8 * (t & (STAGES - 1)));
    }
}

__device__ __forceinline__ uint32_t gemm_mainloop(
    const __half* __restrict__ Ag, const __half* __restrict__ Bg,
    int lda, int ldb, int row0, int nrow0, int tiles, uint32_t sb)
{
    const int tid = threadIdx.x;
    const int wid = tid >> 5;

    if (wid == 0) TC_ALLOC(sb, 256);
    if (tid == 0) {
        #pragma unroll
        for (int s = 0; s < STAGES; ++s)
            mbar_init(sb + 128 + 8 * s, 1);     // mma_done
    }
    __syncthreads();
    if (wid == 0) TC_RELINQ();
    uint32_t tmem;
    asm volatile("ld.shared.b32 %0, [%1];" : "=r"(tmem) : "r"(sb));

    uint32_t md_ph = 0;   // per-stage parity bitmask (uniform across threads)
    for (int kt = 0; kt < tiles; ++kt) {
        const int s = kt & (STAGES - 1);
        if (kt >= STAGES) {       // WAR: tile kt-4's MMA (issued iter kt-2) done?
            mbar_wait(sb + 128 + 8 * s, (md_ph >> s) & 1u);
            md_ph ^= 1u << s;
        }
        issue_tile_loads(Ag, Bg, lda, ldb, row0, nrow0, kt * TK,
                         sb + SM_TILES + s * STAGE_BYTES, tid);
        if (kt >= 2) {
            asm volatile("cp.async.wait_group 2;");   // tile kt-2 loads done
            __syncthreads();                          // ... for ALL threads
            if (wid == 0) issue_tile_mma(sb, tmem, kt - 2);
        }
    }
    // Tail: MMA the last two tiles
    asm volatile("cp.async.wait_group 1;");
    __syncthreads();
    if (wid == 0) issue_tile_mma(sb, tmem, tiles - 2);
    asm volatile("cp.async.wait_group 0;");
    __syncthreads();
    if (wid == 0) issue_tile_mma(sb, tmem, tiles - 1);

    // Final commit tracks ALL prior MMAs: one wait suffices.
    const int sl = (tiles - 1) & (STAGES - 1);
    mbar_wait(sb + 128 + 8 * sl, (md_ph >> sl) & 1u);
    TC_FENCE_AFTER();
    return tmem;
}
#endif  // HAS_TC

// ---------------------------------------------------------------------------
// Fallback (non-'a' PTX pass): wmma fp16 m16n16k16, 128x128 half-tile helper.
// ---------------------------------------------------------------------------
__device__ __forceinline__ void fb_gemm128(
    const __half* __restrict__ Ag, int lda, const __half* __restrict__ Bg, int ldb,
    int row0, int nrow0, int K, char* smem, float* Cs)
{
    __half* As = reinterpret_cast<__half*>(smem);
    __half* Bs = reinterpret_cast<__half*>(smem + 128 * 40 * 2);
    const int tid = threadIdx.x;
    const int wid = tid >> 5;
    const int wm = wid & 1, wn = wid >> 1;

    wmma::fragment<wmma::accumulator, 16, 16, 16, float> acc[4][2];
    #pragma unroll
    for (int i = 0; i < 4; i++)
        #pragma unroll
        for (int j = 0; j < 2; j++)
            wmma::fill_fragment(acc[i][j], 0.0f);

    for (int kt = 0; kt < K / 32; ++kt) {
        const int kb = kt * 32;
        #pragma unroll
        for (int i = 0; i < 2; ++i) {
            const int v = tid + i * 256;
            const int r = v >> 2, c = (v & 3) * 8;
            *reinterpret_cast<uint4*>(&As[r * 40 + c]) =
                *reinterpret_cast<const uint4*>(&Ag[(size_t)(row0 + r) * lda + kb + c]);
            *reinterpret_cast<uint4*>(&Bs[r * 40 + c]) =
                *reinterpret_cast<const uint4*>(&Bg[(size_t)(nrow0 + r) * ldb + kb + c]);
        }
        __syncthreads();
        #pragma unroll
        for (int kk = 0; kk < 32; kk += 16) {
            wmma::fragment<wmma::matrix_a, 16, 16, 16, __half, wmma::row_major> af[4];
            wmma::fragment<wmma::matrix_b, 16, 16, 16, __half, wmma::col_major> bf[2];
            #pragma unroll
            for (int fm = 0; fm < 4; fm++)
                wmma::load_matrix_sync(af[fm], &As[(wm * 64 + fm * 16) * 40 + kk], 40);
            #pragma unroll
            for (int fn = 0; fn < 2; fn++)
                wmma::load_matrix_sync(bf[fn], &Bs[(wn * 32 + fn * 16) * 40 + kk], 40);
            #pragma unroll
            for (int fm = 0; fm < 4; fm++)
                #pragma unroll
                for (int fn = 0; fn < 2; fn++)
                    wmma::mma_sync(acc[fm][fn], af[fm], bf[fn], acc[fm][fn]);
        }
        __syncthreads();
    }
    #pragma unroll
    for (int fm = 0; fm < 4; fm++)
        #pragma unroll
        for (int fn = 0; fn < 2; fn++)
            wmma::store_matrix_sync(&Cs[(wm * 64 + fm * 16) * 132 + wn * 32 + fn * 16],
                                    acc[fm][fn], 132, wmma::mem_row_major);
    __syncthreads();
}

// ---------------------------------------------------------------------------
// GEMM1: enc = tanh(h @ Wh^T + b1) -> g_enc (fp32) + g_ench (fp16)
// grid: (Dn/TN=4, Bn/TM=32), 256 threads
// ---------------------------------------------------------------------------
__global__ __launch_bounds__(256) void gemm1_kernel(const float* __restrict__ b1)
{
    extern __shared__ __align__(1024) char smem[];
    const int row0 = blockIdx.y * TM;
    const int col0 = blockIdx.x * TN;
    const int tid = threadIdx.x;
    const int wid = tid >> 5;

#if HAS_TC
    const uint32_t sb = smem_u32(smem);
    const uint32_t tmem = gemm_mainloop(g_h, g_Wh, Nn, Nn, row0, col0, Nn / TK, sb);

    const int lane = tid & 31;
    const int team = wid >> 2;
    const int r = ((wid & 3) << 5) + lane;
    const size_t grow = row0 + r;
    #pragma unroll
    for (int chunk = 0; chunk < 4; ++chunk) {
        const int c0 = team * 128 + chunk * 32;
        uint32_t regs[32];
        LDTM_X32(regs, tmem + c0);
        TC_WAIT_LD();
        #pragma unroll
        for (int j = 0; j < 32; j += 2) {
            const int d = col0 + c0 + j;
            const float e0 = tanhf(__uint_as_float(regs[j])     + b1[d]);
            const float e1 = tanhf(__uint_as_float(regs[j + 1]) + b1[d + 1]);
            g_enc[grow * Dn + d]     = e0;
            g_enc[grow * Dn + d + 1] = e1;
            *reinterpret_cast<__half2*>(&g_ench[grow * Dn + d]) = __floats2half2_rn(e0, e1);
        }
    }
    TC_FENCE_BEFORE();
    __syncthreads();
    if (wid == 0) TC_DEALLOC(tmem, 256);
#else
    float* Cs = reinterpret_cast<float*>(smem);
    for (int hf = 0; hf < 2; ++hf) {
        fb_gemm128(g_h, Nn, g_Wh, Nn, row0, col0 + hf * 128, Nn, smem, Cs);
        #pragma unroll 4
        for (int t = 0; t < 32; ++t) {
            const int p = tid + t * 256;
            const int r = p >> 6, c2 = (p & 63) * 2;
            const int d = col0 + hf * 128 + c2;
            const size_t grow = row0 + r;
            const float e0 = tanhf(Cs[r * 132 + c2]     + b1[d]);
            const float e1 = tanhf(Cs[r * 132 + c2 + 1] + b1[d + 1]);
            g_enc[grow * Dn + d]     = e0;
            g_enc[grow * Dn + d + 1] = e1;
            *reinterpret_cast<__half2*>(&g_ench[grow * Dn + d]) = __floats2half2_rn(e0, e1);
        }
        __syncthreads();
    }
#endif
}

// ---------------------------------------------------------------------------
// GEMM2: recon = ench @ Wt^T + b2 (never stored); fused masked-MSE partials
// grid: (Nn/TN=32, Bn/TM=32)
// ---------------------------------------------------------------------------
__global__ __launch_bounds__(256) void gemm2_kernel(
    const float* __restrict__ x, const float* __restrict__ b2)
{
    extern __shared__ __align__(1024) char smem[];
    const int row0 = blockIdx.y * TM;
    const int nb = blockIdx.x;
    const int n0 = nb * TN;
    const int tid = threadIdx.x;
    const int wid = tid >> 5;
    const int lane = tid & 31;

#if HAS_TC
    const uint32_t sb = smem_u32(smem);
    const uint32_t tmem = gemm_mainloop(g_ench, g_Wt, Dn, Dn, row0, n0, Dn / TK, sb);

    const int team = wid >> 2;
    const int r = ((wid & 3) << 5) + lane;
    const size_t grow = row0 + r;
    float err = 0.f, cnt = 0.f;
    #pragma unroll
    for (int chunk = 0; chunk < 4; ++chunk) {
        const int c0 = team * 128 + chunk * 32;
        uint32_t regs[32];
        LDTM_X32(regs, tmem + c0);
        TC_WAIT_LD();
        const float* xr = x + grow * Nn + n0 + c0;
        const float* b2r = b2 + n0 + c0;
        #pragma unroll
        for (int j = 0; j < 32; ++j) {
            const float recon = __uint_as_float(regs[j]) + b2r[j];
            const float xv = xr[j];
            if (xv != 0.0f) {
                const float d = xv - recon;
                err += d * d;
                cnt += 1.0f;
            }
        }
    }
    g_errp[grow * 64 + nb * 2 + team] = err;
    g_cntp[grow * 64 + nb * 2 + team] = cnt;

    TC_FENCE_BEFORE();
    __syncthreads();
    if (wid == 0) TC_DEALLOC(tmem, 256);
#else
    float* Cs = reinterpret_cast<float*>(smem);
    for (int hf = 0; hf < 2; ++hf) {
        fb_gemm128(g_ench, Dn, g_Wt, Dn, row0, n0 + hf * 128, Dn, smem, Cs);
        for (int rr = 0; rr < 16; ++rr) {
            const int r = wid * 16 + rr;
            const size_t brow = row0 + r;
            float err = 0.f, cnt = 0.f;
            #pragma unroll
            for (int s4 = 0; s4 < 4; ++s4) {
                const int c = s4 * 32 + lane;
                const float recon = Cs[r * 132 + c] + b2[n0 + hf * 128 + c];
                const float xv = x[brow * Nn + n0 + hf * 128 + c];
                if (xv != 0.0f) {
                    const float d = xv - recon;
                    err += d * d;
                    cnt += 1.0f;
                }
            }
            #pragma unroll
            for (int o = 16; o; o >>= 1) {
                err += __shfl_xor_sync(0xffffffffu, err, o);
                cnt += __shfl_xor_sync(0xffffffffu, cnt, o);
            }
            if (lane == 0) {
                g_errp[brow * 64 + nb * 2 + hf] = err;
                g_cntp[brow * 64 + nb * 2 + hf] = cnt;
            }
        }
        __syncthreads();
    }
#endif
}

// ---------------------------------------------------------------------------
// Pre-pass conversions
// ---------------------------------------------------------------------------
__global__ void conv_h_kernel(const float4* __restrict__ x, const float4* __restrict__ m)
{
    const size_t i = (size_t)blockIdx.x * blockDim.x + threadIdx.x;
    const float4 xv = x[i], mv = m[i];
    __half2* o = reinterpret_cast<__half2*>(g_h) + 2 * i;
    o[0] = __floats2half2_rn(xv.x * mv.x * DROP_SCALE, xv.y * mv.y * DROP_SCALE);
    o[1] = __floats2half2_rn(xv.z * mv.z * DROP_SCALE, xv.w * mv.w * DROP_SCALE);
}

// Merged W prep: read W once; emit g_Wh (same layout) and g_Wt (transposed)
__global__ void wprep_kernel(const float* __restrict__ W)
{
    __shared__ __half t[32][33];
    const int n0 = blockIdx.x * 32, d0 = blockIdx.y * 32;
    const int tx = threadIdx.x, ty = threadIdx.y;
    #pragma unroll
    for (int i = ty; i < 32; i += 8) {
        const __half v = __float2half_rn(W[(size_t)(d0 + i) * Nn + n0 + tx]);
        g_Wh[(size_t)(d0 + i) * Nn + n0 + tx] = v;
        t[i][tx] = v;
    }
    __syncthreads();
    #pragma unroll
    for (int i = ty; i < 32; i += 8)
        g_Wt[(size_t)(n0 + i) * Dn + d0 + tx] = t[tx][i];
}

// ---------------------------------------------------------------------------
// LayerNorm over D per row -> out[0 : B*D)
// ---------------------------------------------------------------------------
__global__ __launch_bounds__(256) void ln_kernel(
    const float* __restrict__ gamma, const float* __restrict__ beta,
    float* __restrict__ out)
{
    const int row = blockIdx.x;
    const int tid = threadIdx.x;
    const float* rp = g_enc + (size_t)row * Dn;
    float e[4], s = 0.f, ss = 0.f;
    #pragma unroll
    for (int j = 0; j < 4; j++) {
        e[j] = rp[tid + j * 256];
        s += e[j];
        ss += e[j] * e[j];
    }
    #pragma unroll
    for (int o = 16; o; o >>= 1) {
        s  += __shfl_xor_sync(0xffffffffu, s, o);
        ss += __shfl_xor_sync(0xffffffffu, ss, o);
    }
    __shared__ float r1[8], r2[8];
    __shared__ float sh_mu, sh_rstd;
    if ((tid & 31) == 0) { r1[tid >> 5] = s; r2[tid >> 5] = ss; }
    __syncthreads();
    if (tid == 0) {
        float ts = 0.f, tss = 0.f;
        #pragma unroll
        for (int k = 0; k < 8; k++) { ts += r1[k]; tss += r2[k]; }
        const float mu = ts * (1.0f / Dn);
        const float var = tss * (1.0f / Dn) - mu * mu;
        sh_mu = mu;
        sh_rstd = rsqrtf(var + EPS);
    }
    __syncthreads();
    const float mu = sh_mu, rstd = sh_rstd;
    #pragma unroll
    for (int j = 0; j < 4; j++) {
        const int d = tid + j * 256;
        out[(size_t)row * Dn + d] = (e[j] - mu) * rstd * gamma[d] + beta[d];
    }
}

// ---------------------------------------------------------------------------
// Loss reduction (fixed order, no atomics)
// ---------------------------------------------------------------------------
__global__ void reduce1_kernel()
{
    const int row = blockIdx.x * 128 + threadIdx.x;
    float err = 0.f, cnt = 0.f;
    #pragma unroll 8
    for (int j = 0; j < 64; ++j) {
        err += g_errp[(size_t)row * 64 + j];
        cnt += g_cntp[(size_t)row * 64 + j];
    }
    __shared__ float sh[128];
    sh[threadIdx.x] = err / cnt;
    __syncthreads();
    for (int s = 64; s > 0; s >>= 1) {
        if (threadIdx.x < s) sh[threadIdx.x] += sh[threadIdx.x + s];
        __syncthreads();
    }
    if (threadIdx.x == 0) g_lossp[blockIdx.x] = sh[0];
}

__global__ void reduce2_kernel(float* __restrict__ out)
{
    float v = g_lossp[threadIdx.x];
    #pragma unroll
    for (int o = 16; o; o >>= 1) v += __shfl_xor_sync(0xffffffffu, v, o);
    if (threadIdx.x == 0) out[(size_t)Bn * Dn] = v;
}

// ---------------------------------------------------------------------------
// Entry. Inputs: x, drop_mask, W, b1, b2, gamma, beta.
// Output: final [B, D] then recon_loss scalar at out[B*D].
// ---------------------------------------------------------------------------
extern "C" void kernel_launch(void* const* d_in, const int* in_sizes, int n_in,
                              void* d_out, int out_size)
{
    const float* x     = (const float*)d_in[0];
    const float* mask  = (const float*)d_in[1];
    const float* W     = (const float*)d_in[2];
    const float* b1    = (const float*)d_in[3];
    const float* b2    = (const float*)d_in[4];
    const float* gamma = (const float*)d_in[5];
    const float* beta  = (const float*)d_in[6];
    float* out = (float*)d_out;

    cudaFuncSetAttribute(gemm1_kernel, cudaFuncAttributeMaxDynamicSharedMemorySize, SMEM_BYTES);
    cudaFuncSetAttribute(gemm2_kernel, cudaFuncAttributeMaxDynamicSharedMemorySize, SMEM_BYTES);

    conv_h_kernel<<<(Bn * (Nn / 4)) / 256, 256>>>((const float4*)x, (const float4*)mask);
    wprep_kernel<<<dim3(Nn / 32, Dn / 32), dim3(32, 8)>>>(W);
    gemm1_kernel<<<dim3(Dn / TN, Bn / TM), 256, SMEM_BYTES>>>(b1);
    ln_kernel<<<Bn, 256>>>(gamma, beta, out);
    gemm2_kernel<<<dim3(Nn / TN, Bn / TM), 256, SMEM_BYTES>>>(x, b2);
    reduce1_kernel<<<32, 128>>>();
    reduce2_kernel<<<1, 32>>>(out);
}